// round 2
// baseline (speedup 1.0000x reference)
#include <cuda_runtime.h>
#include <cstdint>
#include <math.h>

#define VOCAB 32000
#define EMB   128
#define HID   256
#define G4    1024   // 4*HID
#define BSZ   8
#define SEQ   1024
#define TOK   (BSZ*SEQ) // 8192

// Scratch (device globals — no allocation allowed)
__device__ float g_xw[(size_t)TOK * G4];       // 33.5 MB: xW + bias, (b,s,4H)
__device__ float g_hidden[(size_t)TOK * HID];  // 8.4 MB: hidden_seq, (b,s,H)
__device__ float g_h[BSZ][2][HID];             // h double buffer per batch
__device__ unsigned g_sync[BSZ * (SEQ + 1)];   // per-step arrival counters

// ---------------------------------------------------------------------------
// Kernel A: x = embed(sentence); g_xw = x @ W + bias.
// Also zeroes g_sync for the recurrence kernel (deterministic across replays).
// Tile: 64 tokens x 128 gate-cols per block, K=128 in 4 chunks of 32.
// ---------------------------------------------------------------------------
__global__ __launch_bounds__(256) void embed_xw_kernel(
    const int* __restrict__ sentence,
    const float* __restrict__ emb,
    const float* __restrict__ W,
    const float* __restrict__ bias)
{
    __shared__ int   toks[64];
    __shared__ float xs[64][33];    // padded
    __shared__ float ws[32][128];

    const int tid = threadIdx.x;
    const int n0 = blockIdx.x * 128;
    const int m0 = blockIdx.y * 64;

    // zero the sync counters (grid has plenty of threads)
    {
        int gid = (blockIdx.y * gridDim.x + blockIdx.x) * 256 + tid;
        if (gid < BSZ * (SEQ + 1)) g_sync[gid] = 0u;
    }

    if (tid < 64) toks[tid] = sentence[m0 + tid];
    __syncthreads();

    const int tn = tid & 15;   // 0..15 -> 8 cols each
    const int tm = tid >> 4;   // 0..15 -> 4 rows each

    float acc[4][8];
    #pragma unroll
    for (int i = 0; i < 4; i++)
        #pragma unroll
        for (int jj = 0; jj < 8; jj++) acc[i][jj] = 0.f;

    for (int kc = 0; kc < 4; kc++) {
        #pragma unroll
        for (int q = 0; q < 2; q++) {
            int idx = tid + q * 256;          // 0..511
            int m = idx >> 3, k4 = idx & 7;
            float4 v = *reinterpret_cast<const float4*>(
                &emb[(size_t)toks[m] * EMB + kc * 32 + k4 * 4]);
            xs[m][k4 * 4 + 0] = v.x; xs[m][k4 * 4 + 1] = v.y;
            xs[m][k4 * 4 + 2] = v.z; xs[m][k4 * 4 + 3] = v.w;
        }
        #pragma unroll
        for (int q = 0; q < 4; q++) {
            int idx = tid + q * 256;          // 0..1023
            int k = idx >> 5, c4 = idx & 31;
            *reinterpret_cast<float4*>(&ws[k][c4 * 4]) =
                *reinterpret_cast<const float4*>(
                    &W[(size_t)(kc * 32 + k) * G4 + n0 + c4 * 4]);
        }
        __syncthreads();
        #pragma unroll
        for (int k = 0; k < 32; k++) {
            float4 b0 = *reinterpret_cast<const float4*>(&ws[k][tn * 8]);
            float4 b1 = *reinterpret_cast<const float4*>(&ws[k][tn * 8 + 4]);
            #pragma unroll
            for (int i = 0; i < 4; i++) {
                float a = xs[tm * 4 + i][k];
                acc[i][0] += a * b0.x; acc[i][1] += a * b0.y;
                acc[i][2] += a * b0.z; acc[i][3] += a * b0.w;
                acc[i][4] += a * b1.x; acc[i][5] += a * b1.y;
                acc[i][6] += a * b1.z; acc[i][7] += a * b1.w;
            }
        }
        __syncthreads();
    }

    #pragma unroll
    for (int i = 0; i < 4; i++) {
        size_t row = (size_t)(m0 + tm * 4 + i);
        #pragma unroll
        for (int jj = 0; jj < 8; jj++) {
            int col = n0 + tn * 8 + jj;
            g_xw[row * G4 + col] = acc[i][jj] + bias[col];
        }
    }
}

// ---------------------------------------------------------------------------
// Kernel B: LSTM recurrence, NO clusters.
// 64 CTAs = 8 batches x 8 CTAs (all wave-1 resident: 64 < 148 SMs).
// Within a batch, CTA rank r owns hidden units [32r,32r+32) = 128 gate cols.
// U slice lives in REGISTERS (64 floats/thread x 512 threads = 256x128).
// Per step: dot(h,Ucol) 4-way K-split + shfl reduce -> warp0 activations ->
// h written to gmem double buffer -> per-step L2 counter barrier
// (threadfence + atomicAdd / volatile poll). h is read back via __ldcg (L2).
// ---------------------------------------------------------------------------
__device__ __forceinline__ float fsigmoid(float x) {
    return __fdividef(1.f, 1.f + __expf(-x));
}
__device__ __forceinline__ float ftanh(float x) {
    return __fdividef(2.f, 1.f + __expf(-2.f * x)) - 1.f;
}

__global__ __launch_bounds__(512, 1) void lstm_kernel(const float* __restrict__ U)
{
    __shared__ float gates_s[128];

    const int tid  = threadIdx.x;
    const int b    = blockIdx.x >> 3;
    const int rank = blockIdx.x & 7;
    const int H_lo = rank * 32;

    const int j    = tid >> 2;      // local gate column 0..127
    const int p    = tid & 3;       // K partition 0..3 (64 each)
    const int gate = j >> 5;        // 0:i 1:f 2:g 3:o
    const int unit = j & 31;
    const int gcol = gate * HID + H_lo + unit;

    // this thread's U column slice in registers
    float u[64];
    #pragma unroll
    for (int i = 0; i < 64; i++)
        u[i] = U[(size_t)(p * 64 + i) * G4 + gcol];

    volatile unsigned* sync = g_sync + b * (SEQ + 1);

    // init: zero own h slice of slot 0, then barrier 0
    if (tid < 32) {
        g_h[b][0][H_lo + tid] = 0.f;
        __threadfence();
    }
    __syncthreads();
    if (tid == 0) atomicAdd((unsigned*)&sync[0], 1u);

    float c_reg = 0.f;               // cell state (warp0, lane=unit)
    float xw_next = 0.f;
    const float* xwb = &g_xw[(size_t)b * SEQ * G4 + gcol];
    if (p == 0) xw_next = __ldg(xwb);

    for (int t = 0; t < SEQ; t++) {
        // wait until all 8 CTAs of this batch published step-t inputs
        if (tid == 0) {
            while (sync[t] < 8u) { }
        }
        __syncthreads();

        float xw_cur = xw_next;
        if (p == 0 && t + 1 < SEQ)
            xw_next = __ldg(xwb + (size_t)(t + 1) * G4);  // prefetch

        // dot over this thread's 64 K values (h from L2, never L1)
        const float4* h4 = reinterpret_cast<const float4*>(&g_h[b][t & 1][p * 64]);
        float a0 = 0.f, a1 = 0.f, a2 = 0.f, a3 = 0.f;
        #pragma unroll
        for (int i = 0; i < 16; i++) {
            float4 hv = __ldcg(&h4[i]);
            a0 += hv.x * u[4 * i + 0];
            a1 += hv.y * u[4 * i + 1];
            a2 += hv.z * u[4 * i + 2];
            a3 += hv.w * u[4 * i + 3];
        }
        float acc = (a0 + a1) + (a2 + a3);
        acc += __shfl_xor_sync(0xffffffffu, acc, 1);
        acc += __shfl_xor_sync(0xffffffffu, acc, 2);
        if (p == 0) gates_s[j] = xw_cur + acc;
        __syncthreads();

        if (tid < 32) {
            float iv = fsigmoid(gates_s[tid]);
            float fv = fsigmoid(gates_s[32 + tid]);
            float gv = ftanh(gates_s[64 + tid]);
            float ov = fsigmoid(gates_s[96 + tid]);
            c_reg = fv * c_reg + iv * gv;
            float hv = ov * ftanh(c_reg);

            g_hidden[((size_t)b * SEQ + t) * HID + H_lo + tid] = hv;  // persist
            g_h[b][(t + 1) & 1][H_lo + tid] = hv;                     // next-step h
            __threadfence();
        }
        __syncthreads();   // all lanes' stores+fences done; also WAR on gates_s
        if (tid == 0) atomicAdd((unsigned*)&sync[t + 1], 1u);
    }
}

// ---------------------------------------------------------------------------
// Kernel C: out = g_hidden(8192x256) @ w_linear(256x32000) + bias
// Tiles 128x128xK16, 256 threads, 8x8 microtile, 2 CTAs/SM.
// ---------------------------------------------------------------------------
__global__ __launch_bounds__(256, 2) void out_gemm_kernel(
    const float* __restrict__ Bw,
    const float* __restrict__ bias,
    float* __restrict__ C)
{
    __shared__ float As[16][132];   // transposed A tile, padded
    __shared__ float Bs[16][128];

    const int tid = threadIdx.x;
    const int n0 = blockIdx.x * 128;
    const int m0 = blockIdx.y * 128;
    const int tx = tid & 15, ty = tid >> 4;
    const float* A = g_hidden;

    float acc[8][8];
    #pragma unroll
    for (int i = 0; i < 8; i++)
        #pragma unroll
        for (int jj = 0; jj < 8; jj++) acc[i][jj] = 0.f;

    for (int kt = 0; kt < 16; kt++) {
        #pragma unroll
        for (int q = 0; q < 2; q++) {
            int idx = tid + q * 256;        // 0..511
            int m = idx >> 2, k4 = idx & 3;
            float4 v = *reinterpret_cast<const float4*>(
                &A[(size_t)(m0 + m) * HID + kt * 16 + k4 * 4]);
            As[k4 * 4 + 0][m] = v.x; As[k4 * 4 + 1][m] = v.y;
            As[k4 * 4 + 2][m] = v.z; As[k4 * 4 + 3][m] = v.w;
        }
        #pragma unroll
        for (int q = 0; q < 2; q++) {
            int idx = tid + q * 256;
            int k = idx >> 5, c4 = idx & 31;
            *reinterpret_cast<float4*>(&Bs[k][c4 * 4]) =
                *reinterpret_cast<const float4*>(
                    &Bw[(size_t)(kt * 16 + k) * VOCAB + n0 + c4 * 4]);
        }
        __syncthreads();
        #pragma unroll
        for (int k = 0; k < 16; k++) {
            float4 a0 = *reinterpret_cast<const float4*>(&As[k][ty * 8]);
            float4 a1 = *reinterpret_cast<const float4*>(&As[k][ty * 8 + 4]);
            float4 b0 = *reinterpret_cast<const float4*>(&Bs[k][tx * 8]);
            float4 b1 = *reinterpret_cast<const float4*>(&Bs[k][tx * 8 + 4]);
            float av[8] = {a0.x, a0.y, a0.z, a0.w, a1.x, a1.y, a1.z, a1.w};
            float bv[8] = {b0.x, b0.y, b0.z, b0.w, b1.x, b1.y, b1.z, b1.w};
            #pragma unroll
            for (int i = 0; i < 8; i++)
                #pragma unroll
                for (int jj = 0; jj < 8; jj++)
                    acc[i][jj] += av[i] * bv[jj];
        }
        __syncthreads();
    }

    float4 bb0 = *reinterpret_cast<const float4*>(&bias[n0 + tx * 8]);
    float4 bb1 = *reinterpret_cast<const float4*>(&bias[n0 + tx * 8 + 4]);
    #pragma unroll
    for (int i = 0; i < 8; i++) {
        size_t row = (size_t)(m0 + ty * 8 + i);
        float4 o0, o1;
        o0.x = acc[i][0] + bb0.x; o0.y = acc[i][1] + bb0.y;
        o0.z = acc[i][2] + bb0.z; o0.w = acc[i][3] + bb0.w;
        o1.x = acc[i][4] + bb1.x; o1.y = acc[i][5] + bb1.y;
        o1.z = acc[i][6] + bb1.z; o1.w = acc[i][7] + bb1.w;
        *reinterpret_cast<float4*>(&C[row * VOCAB + n0 + tx * 8])     = o0;
        *reinterpret_cast<float4*>(&C[row * VOCAB + n0 + tx * 8 + 4]) = o1;
    }
}

// ---------------------------------------------------------------------------
extern "C" void kernel_launch(void* const* d_in, const int* in_sizes, int n_in,
                              void* d_out, int out_size)
{
    const int*   sentence = (const int*)  d_in[0];
    const float* emb      = (const float*)d_in[1];
    const float* W        = (const float*)d_in[2];
    const float* U        = (const float*)d_in[3];
    const float* bias     = (const float*)d_in[4];
    const float* wlin     = (const float*)d_in[5];
    const float* blin     = (const float*)d_in[6];
    float* out = (float*)d_out;
    (void)in_sizes; (void)n_in; (void)out_size;

    // A: embed + xW + bias -> g_xw   (also zeroes g_sync)
    embed_xw_kernel<<<dim3(G4 / 128, TOK / 64), 256>>>(sentence, emb, W, bias);

    // B: recurrence -> g_hidden  (64 CTAs, all wave-1 resident)
    lstm_kernel<<<64, 512>>>(U);

    // C: output projection + bias -> d_out
    out_gemm_kernel<<<dim3(VOCAB / 128, TOK / 128), 256>>>(wlin, blin, out);
}

// round 6
// speedup vs baseline: 1.2672x; 1.2672x over previous
#include <cuda_runtime.h>
#include <cuda_bf16.h>
#include <cstdint>
#include <math.h>

#define VOCAB 32000
#define EMB   128
#define HID   256
#define G4    1024   // 4*HID
#define BSZ   8
#define SEQ   1024
#define TOK   (BSZ*SEQ) // 8192

// Scratch (device globals — no allocation allowed)
__device__ float g_xw[(size_t)TOK * G4];                 // 33.5 MB xW + bias
__device__ float g_h[BSZ][2][HID];                       // h double buffer
__device__ unsigned g_sync[BSZ * (SEQ + 1)];             // per-step counters
__device__ __nv_bfloat16 g_ahi[(size_t)TOK * HID];       // hidden hi (bf16)
__device__ __nv_bfloat16 g_alo[(size_t)TOK * HID];       // hidden lo (bf16)
__device__ __nv_bfloat16 g_bhiT[(size_t)VOCAB * HID];    // w_linear^T hi
__device__ __nv_bfloat16 g_bloT[(size_t)VOCAB * HID];    // w_linear^T lo

__device__ __forceinline__ uint32_t smem_u32(const void* p) {
    uint32_t a;
    asm("{ .reg .u64 t; cvta.to.shared.u64 t, %1; cvt.u32.u64 %0, t; }"
        : "=r"(a) : "l"(p));
    return a;
}

// ---------------------------------------------------------------------------
// Kernel A: x = embed(sentence); g_xw = x @ W + bias. Also zeroes g_sync.
// ---------------------------------------------------------------------------
__global__ __launch_bounds__(256) void embed_xw_kernel(
    const int* __restrict__ sentence,
    const float* __restrict__ emb,
    const float* __restrict__ W,
    const float* __restrict__ bias)
{
    __shared__ int   toks[64];
    __shared__ float xs[64][33];
    __shared__ float ws[32][128];

    const int tid = threadIdx.x;
    const int n0 = blockIdx.x * 128;
    const int m0 = blockIdx.y * 64;

    {
        int gid = (blockIdx.y * gridDim.x + blockIdx.x) * 256 + tid;
        if (gid < BSZ * (SEQ + 1)) g_sync[gid] = 0u;
    }

    if (tid < 64) toks[tid] = sentence[m0 + tid];
    __syncthreads();

    const int tn = tid & 15;
    const int tm = tid >> 4;

    float acc[4][8];
    #pragma unroll
    for (int i = 0; i < 4; i++)
        #pragma unroll
        for (int jj = 0; jj < 8; jj++) acc[i][jj] = 0.f;

    for (int kc = 0; kc < 4; kc++) {
        #pragma unroll
        for (int q = 0; q < 2; q++) {
            int idx = tid + q * 256;
            int m = idx >> 3, k4 = idx & 7;
            float4 v = *reinterpret_cast<const float4*>(
                &emb[(size_t)toks[m] * EMB + kc * 32 + k4 * 4]);
            xs[m][k4 * 4 + 0] = v.x; xs[m][k4 * 4 + 1] = v.y;
            xs[m][k4 * 4 + 2] = v.z; xs[m][k4 * 4 + 3] = v.w;
        }
        #pragma unroll
        for (int q = 0; q < 4; q++) {
            int idx = tid + q * 256;
            int k = idx >> 5, c4 = idx & 31;
            *reinterpret_cast<float4*>(&ws[k][c4 * 4]) =
                *reinterpret_cast<const float4*>(
                    &W[(size_t)(kc * 32 + k) * G4 + n0 + c4 * 4]);
        }
        __syncthreads();
        #pragma unroll
        for (int k = 0; k < 32; k++) {
            float4 b0 = *reinterpret_cast<const float4*>(&ws[k][tn * 8]);
            float4 b1 = *reinterpret_cast<const float4*>(&ws[k][tn * 8 + 4]);
            #pragma unroll
            for (int i = 0; i < 4; i++) {
                float a = xs[tm * 4 + i][k];
                acc[i][0] += a * b0.x; acc[i][1] += a * b0.y;
                acc[i][2] += a * b0.z; acc[i][3] += a * b0.w;
                acc[i][4] += a * b1.x; acc[i][5] += a * b1.y;
                acc[i][6] += a * b1.z; acc[i][7] += a * b1.w;
            }
        }
        __syncthreads();
    }

    #pragma unroll
    for (int i = 0; i < 4; i++) {
        size_t row = (size_t)(m0 + tm * 4 + i);
        #pragma unroll
        for (int jj = 0; jj < 8; jj++) {
            int col = n0 + tn * 8 + jj;
            g_xw[row * G4 + col] = acc[i][jj] + bias[col];
        }
    }
}

// ---------------------------------------------------------------------------
// Kernel A2: transpose + bf16 hi/lo split of w_linear -> g_bhiT/g_bloT [V][H]
// ---------------------------------------------------------------------------
__global__ __launch_bounds__(256) void conv_wT_kernel(const float* __restrict__ w)
{
    __shared__ float s[32][33];
    const int tid = threadIdx.x;
    const int n0 = blockIdx.x * 32;
    const int k0 = blockIdx.y * 32;

    int kk = tid >> 5, nn = tid & 31;
    #pragma unroll
    for (int q = 0; q < 4; q++)
        s[kk + q * 8][nn] = w[(size_t)(k0 + kk + q * 8) * VOCAB + n0 + nn];
    __syncthreads();

    int nn2 = tid >> 3, k4 = (tid & 7) * 4;
    #pragma unroll
    for (int j = 0; j < 4; j++) {
        float x = s[k4 + j][nn2];
        __nv_bfloat16 hi = __float2bfloat16(x);
        __nv_bfloat16 lo = __float2bfloat16(x - __bfloat162float(hi));
        size_t o = (size_t)(n0 + nn2) * HID + k0 + k4 + j;
        g_bhiT[o] = hi;
        g_bloT[o] = lo;
    }
}

// ---------------------------------------------------------------------------
// Kernel B: LSTM recurrence (unchanged; emits bf16 hi/lo hidden).
// ---------------------------------------------------------------------------
__device__ __forceinline__ float fsigmoid(float x) {
    return __fdividef(1.f, 1.f + __expf(-x));
}
__device__ __forceinline__ float ftanh(float x) {
    return __fdividef(2.f, 1.f + __expf(-2.f * x)) - 1.f;
}

__global__ __launch_bounds__(512, 1) void lstm_kernel(const float* __restrict__ U)
{
    __shared__ float gates_s[128];

    const int tid  = threadIdx.x;
    const int b    = blockIdx.x >> 3;
    const int rank = blockIdx.x & 7;
    const int H_lo = rank * 32;

    const int j    = tid >> 2;
    const int p    = tid & 3;
    const int gate = j >> 5;
    const int unit = j & 31;
    const int gcol = gate * HID + H_lo + unit;

    float u[64];
    #pragma unroll
    for (int i = 0; i < 64; i++)
        u[i] = U[(size_t)(p * 64 + i) * G4 + gcol];

    volatile unsigned* sync = g_sync + b * (SEQ + 1);

    if (tid < 32) {
        g_h[b][0][H_lo + tid] = 0.f;
        __threadfence();
    }
    __syncthreads();
    if (tid == 0) atomicAdd((unsigned*)&sync[0], 1u);

    float c_reg = 0.f;
    float xw_next = 0.f;
    const float* xwb = &g_xw[(size_t)b * SEQ * G4 + gcol];
    if (p == 0) xw_next = __ldg(xwb);

    for (int t = 0; t < SEQ; t++) {
        if (tid == 0) {
            while (sync[t] < 8u) { }
        }
        __syncthreads();

        float xw_cur = xw_next;
        if (p == 0 && t + 1 < SEQ)
            xw_next = __ldg(xwb + (size_t)(t + 1) * G4);

        const float4* h4 = reinterpret_cast<const float4*>(&g_h[b][t & 1][p * 64]);
        float a0 = 0.f, a1 = 0.f, a2 = 0.f, a3 = 0.f;
        #pragma unroll
        for (int i = 0; i < 16; i++) {
            float4 hv = __ldcg(&h4[i]);
            a0 += hv.x * u[4 * i + 0];
            a1 += hv.y * u[4 * i + 1];
            a2 += hv.z * u[4 * i + 2];
            a3 += hv.w * u[4 * i + 3];
        }
        float acc = (a0 + a1) + (a2 + a3);
        acc += __shfl_xor_sync(0xffffffffu, acc, 1);
        acc += __shfl_xor_sync(0xffffffffu, acc, 2);
        if (p == 0) gates_s[j] = xw_cur + acc;
        __syncthreads();

        if (tid < 32) {
            float iv = fsigmoid(gates_s[tid]);
            float fv = fsigmoid(gates_s[32 + tid]);
            float gv = ftanh(gates_s[64 + tid]);
            float ov = fsigmoid(gates_s[96 + tid]);
            c_reg = fv * c_reg + iv * gv;
            float hv = ov * ftanh(c_reg);

            size_t o = ((size_t)b * SEQ + t) * HID + H_lo + tid;
            __nv_bfloat16 hb = __float2bfloat16(hv);
            g_ahi[o] = hb;
            g_alo[o] = __float2bfloat16(hv - __bfloat162float(hb));
            g_h[b][(t + 1) & 1][H_lo + tid] = hv;
            __threadfence();
        }
        __syncthreads();
        if (tid == 0) atomicAdd((unsigned*)&sync[t + 1], 1u);
    }
}

// ---------------------------------------------------------------------------
// Kernel C: out projection via warp-level mma.sync (sm_80-class bf16 HMMA).
// C = A(8192x256) @ B^T(32000x256) + bias, hi/lo 3-term split, fp32 accum:
//   D = a_hi*b_hi + a_hi*b_lo + a_lo*b_hi
// CTA tile 128(M)x128(N), 8 warps (4x2), warp tile 32x64, K chunks of 32.
// Smem rows: 64B data + 16B pad (SPITCH=80), static 40KB.
// FIX vs R4: tile fill indexing (row = idx>>2, slot = idx&3) — previous
// version wrote rows 0..255 of a 128-row tile (smem OOB -> illegal access).
// ---------------------------------------------------------------------------
#define SA_HI 0
#define SA_LO 10240
#define SB_HI 20480
#define SB_LO 30720
#define SPITCH 80     // 32 bf16 (64B) + 16B pad

__device__ __forceinline__ void ldm_x4(uint32_t* r, uint32_t addr) {
    asm volatile("ldmatrix.sync.aligned.m8n8.x4.shared.b16 {%0,%1,%2,%3}, [%4];"
        : "=r"(r[0]), "=r"(r[1]), "=r"(r[2]), "=r"(r[3]) : "r"(addr));
}
__device__ __forceinline__ void mma16816(float* c, const uint32_t* a,
                                         uint32_t b0, uint32_t b1) {
    asm volatile("mma.sync.aligned.m16n8k16.row.col.f32.bf16.bf16.f32 "
        "{%0,%1,%2,%3}, {%4,%5,%6,%7}, {%8,%9}, {%0,%1,%2,%3};"
        : "+f"(c[0]), "+f"(c[1]), "+f"(c[2]), "+f"(c[3])
        : "r"(a[0]), "r"(a[1]), "r"(a[2]), "r"(a[3]), "r"(b0), "r"(b1));
}

__global__ __launch_bounds__(256) void out_gemm_mma(
    const float* __restrict__ blin, float* __restrict__ C)
{
    __shared__ __align__(16) char smem[40960];
    const uint32_t sb = smem_u32(smem);
    const int tid  = threadIdx.x;
    const int wid  = tid >> 5, lane = tid & 31;
    const int m0   = blockIdx.x * 128;   // M fastest -> B tile L2-resident
    const int n0   = blockIdx.y * 128;
    const int wm   = (wid & 3) * 32;
    const int wn   = (wid >> 2) * 64;

    float c[2][8][4];
    #pragma unroll
    for (int mi = 0; mi < 2; mi++)
        #pragma unroll
        for (int nt = 0; nt < 8; nt++)
            #pragma unroll
            for (int q = 0; q < 4; q++) c[mi][nt][q] = 0.f;

    const int lr = lane & 15;            // ldmatrix row within 16-row tile
    const int lc = (lane >> 4) * 8;      // ldmatrix k-offset (0 or 8)

    for (int kt = 0; kt < 8; kt++) {     // K = 8 chunks x 32
        __syncthreads();                 // protect previous chunk's reads
        // 128 rows x 64B per tile = 512 x 16B transactions per array
        #pragma unroll
        for (int q = 0; q < 2; q++) {
            int idx = tid + q * 256;     // 0..511
            int row = idx >> 2, slot = idx & 3;        // 4x16B per row
            uint32_t dst = (uint32_t)(row * SPITCH + slot * 16);
            size_t srcA = (size_t)(m0 + row) * HID + kt * 32 + slot * 8;
            size_t srcB = (size_t)(n0 + row) * HID + kt * 32 + slot * 8;
            *reinterpret_cast<float4*>(smem + SA_HI + dst) =
                *reinterpret_cast<const float4*>(&g_ahi[srcA]);
            *reinterpret_cast<float4*>(smem + SA_LO + dst) =
                *reinterpret_cast<const float4*>(&g_alo[srcA]);
            *reinterpret_cast<float4*>(smem + SB_HI + dst) =
                *reinterpret_cast<const float4*>(&g_bhiT[srcB]);
            *reinterpret_cast<float4*>(smem + SB_LO + dst) =
                *reinterpret_cast<const float4*>(&g_bloT[srcB]);
        }
        __syncthreads();

        #pragma unroll
        for (int ks = 0; ks < 2; ks++) { // two k16 steps per chunk
            const int k0 = ks * 16;
            uint32_t a_hi[2][4], a_lo[2][4];
            #pragma unroll
            for (int mi = 0; mi < 2; mi++) {
                uint32_t ad = sb + SA_HI +
                    (uint32_t)((wm + mi * 16 + lr) * SPITCH + (k0 + lc) * 2);
                ldm_x4(a_hi[mi], ad);
                ldm_x4(a_lo[mi], ad + (SA_LO - SA_HI));
            }
            uint32_t b_hi[4][4], b_lo[4][4];
            #pragma unroll
            for (int nj = 0; nj < 4; nj++) {
                uint32_t bd = sb + SB_HI +
                    (uint32_t)((wn + nj * 16 + lr) * SPITCH + (k0 + lc) * 2);
                ldm_x4(b_hi[nj], bd);
                ldm_x4(b_lo[nj], bd + (SB_LO - SB_HI));
            }
            #pragma unroll
            for (int mi = 0; mi < 2; mi++) {
                #pragma unroll
                for (int nj = 0; nj < 4; nj++) {
                    // n-tile 2*nj uses frags {r0,r2}; 2*nj+1 uses {r1,r3}
                    mma16816(c[mi][2*nj],   a_hi[mi], b_hi[nj][0], b_hi[nj][2]);
                    mma16816(c[mi][2*nj],   a_hi[mi], b_lo[nj][0], b_lo[nj][2]);
                    mma16816(c[mi][2*nj],   a_lo[mi], b_hi[nj][0], b_hi[nj][2]);
                    mma16816(c[mi][2*nj+1], a_hi[mi], b_hi[nj][1], b_hi[nj][3]);
                    mma16816(c[mi][2*nj+1], a_hi[mi], b_lo[nj][1], b_lo[nj][3]);
                    mma16816(c[mi][2*nj+1], a_lo[mi], b_hi[nj][1], b_hi[nj][3]);
                }
            }
        }
    }

    // Epilogue: direct register->gmem, frag layout
    //   row = (lane>>2) [+8 for regs 2,3], col = (lane&3)*2 + {0,1}
    const int rbase = m0 + wm + (lane >> 2);
    const int cbase = n0 + wn + (lane & 3) * 2;
    #pragma unroll
    for (int mi = 0; mi < 2; mi++) {
        #pragma unroll
        for (int nt = 0; nt < 8; nt++) {
            int col = cbase + nt * 8;
            float2 bb = *reinterpret_cast<const float2*>(&blin[col]);
            int r0 = rbase + mi * 16;
            float2 v0, v1;
            v0.x = c[mi][nt][0] + bb.x; v0.y = c[mi][nt][1] + bb.y;
            v1.x = c[mi][nt][2] + bb.x; v1.y = c[mi][nt][3] + bb.y;
            *reinterpret_cast<float2*>(&C[(size_t)r0 * VOCAB + col]) = v0;
            *reinterpret_cast<float2*>(&C[(size_t)(r0 + 8) * VOCAB + col]) = v1;
        }
    }
}

// ---------------------------------------------------------------------------
extern "C" void kernel_launch(void* const* d_in, const int* in_sizes, int n_in,
                              void* d_out, int out_size)
{
    const int*   sentence = (const int*)  d_in[0];
    const float* emb      = (const float*)d_in[1];
    const float* W        = (const float*)d_in[2];
    const float* U        = (const float*)d_in[3];
    const float* bias     = (const float*)d_in[4];
    const float* wlin     = (const float*)d_in[5];
    const float* blin     = (const float*)d_in[6];
    float* out = (float*)d_out;
    (void)in_sizes; (void)n_in; (void)out_size;

    // A: embed + xW + bias -> g_xw (also zeroes g_sync)
    embed_xw_kernel<<<dim3(G4 / 128, TOK / 64), 256>>>(sentence, emb, W, bias);

    // A2: w_linear transpose + bf16 split
    conv_wT_kernel<<<dim3(VOCAB / 32, HID / 32), 256>>>(wlin);

    // B: recurrence -> g_ahi/g_alo
    lstm_kernel<<<64, 512>>>(U);

    // C: mma.sync output projection + bias -> d_out
    out_gemm_mma<<<dim3(TOK / 128, VOCAB / 128), 256>>>(blin, out);
}

// round 7
// speedup vs baseline: 2.6997x; 2.1304x over previous
#include <cuda_runtime.h>
#include <cuda_bf16.h>
#include <cstdint>
#include <math.h>

#define VOCAB 32000
#define EMB   128
#define HID   256
#define G4    1024   // 4*HID
#define BSZ   8
#define SEQ   1024
#define TOK   (BSZ*SEQ) // 8192

// Scratch (device globals — no allocation allowed)
__device__ float g_xw[(size_t)TOK * G4];                 // 33.5 MB xW + bias
__device__ __nv_bfloat16 g_ahi[(size_t)TOK * HID];       // hidden hi (bf16)
__device__ __nv_bfloat16 g_alo[(size_t)TOK * HID];       // hidden lo (bf16)
__device__ __nv_bfloat16 g_bhiT[(size_t)VOCAB * HID];    // w_linear^T hi
__device__ __nv_bfloat16 g_bloT[(size_t)VOCAB * HID];    // w_linear^T lo

__device__ __forceinline__ uint32_t smem_u32(const void* p) {
    uint32_t a;
    asm("{ .reg .u64 t; cvta.to.shared.u64 t, %1; cvt.u32.u64 %0, t; }"
        : "=r"(a) : "l"(p));
    return a;
}

// ---------------------------------------------------------------------------
// Kernel A: x = embed(sentence); g_xw = x @ W + bias.
// ---------------------------------------------------------------------------
__global__ __launch_bounds__(256) void embed_xw_kernel(
    const int* __restrict__ sentence,
    const float* __restrict__ emb,
    const float* __restrict__ W,
    const float* __restrict__ bias)
{
    __shared__ int   toks[64];
    __shared__ float xs[64][33];
    __shared__ float ws[32][128];

    const int tid = threadIdx.x;
    const int n0 = blockIdx.x * 128;
    const int m0 = blockIdx.y * 64;

    if (tid < 64) toks[tid] = sentence[m0 + tid];
    __syncthreads();

    const int tn = tid & 15;
    const int tm = tid >> 4;

    float acc[4][8];
    #pragma unroll
    for (int i = 0; i < 4; i++)
        #pragma unroll
        for (int jj = 0; jj < 8; jj++) acc[i][jj] = 0.f;

    for (int kc = 0; kc < 4; kc++) {
        #pragma unroll
        for (int q = 0; q < 2; q++) {
            int idx = tid + q * 256;
            int m = idx >> 3, k4 = idx & 7;
            float4 v = *reinterpret_cast<const float4*>(
                &emb[(size_t)toks[m] * EMB + kc * 32 + k4 * 4]);
            xs[m][k4 * 4 + 0] = v.x; xs[m][k4 * 4 + 1] = v.y;
            xs[m][k4 * 4 + 2] = v.z; xs[m][k4 * 4 + 3] = v.w;
        }
        #pragma unroll
        for (int q = 0; q < 4; q++) {
            int idx = tid + q * 256;
            int k = idx >> 5, c4 = idx & 31;
            *reinterpret_cast<float4*>(&ws[k][c4 * 4]) =
                *reinterpret_cast<const float4*>(
                    &W[(size_t)(kc * 32 + k) * G4 + n0 + c4 * 4]);
        }
        __syncthreads();
        #pragma unroll
        for (int k = 0; k < 32; k++) {
            float4 b0 = *reinterpret_cast<const float4*>(&ws[k][tn * 8]);
            float4 b1 = *reinterpret_cast<const float4*>(&ws[k][tn * 8 + 4]);
            #pragma unroll
            for (int i = 0; i < 4; i++) {
                float a = xs[tm * 4 + i][k];
                acc[i][0] += a * b0.x; acc[i][1] += a * b0.y;
                acc[i][2] += a * b0.z; acc[i][3] += a * b0.w;
                acc[i][4] += a * b1.x; acc[i][5] += a * b1.y;
                acc[i][6] += a * b1.z; acc[i][7] += a * b1.w;
            }
        }
        __syncthreads();
    }

    #pragma unroll
    for (int i = 0; i < 4; i++) {
        size_t row = (size_t)(m0 + tm * 4 + i);
        #pragma unroll
        for (int jj = 0; jj < 8; jj++) {
            int col = n0 + tn * 8 + jj;
            g_xw[row * G4 + col] = acc[i][jj] + bias[col];
        }
    }
}

// ---------------------------------------------------------------------------
// Kernel A2: transpose + bf16 hi/lo split of w_linear -> g_bhiT/g_bloT [V][H]
// ---------------------------------------------------------------------------
__global__ __launch_bounds__(256) void conv_wT_kernel(const float* __restrict__ w)
{
    __shared__ float s[32][33];
    const int tid = threadIdx.x;
    const int n0 = blockIdx.x * 32;
    const int k0 = blockIdx.y * 32;

    int kk = tid >> 5, nn = tid & 31;
    #pragma unroll
    for (int q = 0; q < 4; q++)
        s[kk + q * 8][nn] = w[(size_t)(k0 + kk + q * 8) * VOCAB + n0 + nn];
    __syncthreads();

    int nn2 = tid >> 3, k4 = (tid & 7) * 4;
    #pragma unroll
    for (int j = 0; j < 4; j++) {
        float x = s[k4 + j][nn2];
        __nv_bfloat16 hi = __float2bfloat16(x);
        __nv_bfloat16 lo = __float2bfloat16(x - __bfloat162float(hi));
        size_t o = (size_t)(n0 + nn2) * HID + k0 + k4 + j;
        g_bhiT[o] = hi;
        g_bloT[o] = lo;
    }
}

// ---------------------------------------------------------------------------
// Kernel B: LSTM recurrence — 8 clusters of 8 CTAs (DSMEM h broadcast).
// Warp w: p = w&3 (K quarter, shared by all lanes -> LDS broadcast),
//         gate = w>>2, unit = lane. Partial sums reduced via smem.
// Per step: dot -> gpart -> syncthreads -> warp0 activations + DSMEM
// broadcast of h slice to all 8 CTAs -> barrier.cluster.
// ---------------------------------------------------------------------------
__device__ __forceinline__ float fsigmoid(float x) {
    return __fdividef(1.f, 1.f + __expf(-x));
}
__device__ __forceinline__ float ftanh(float x) {
    return __fdividef(2.f, 1.f + __expf(-2.f * x)) - 1.f;
}

__global__ void __cluster_dims__(8, 1, 1) __launch_bounds__(512, 1)
lstm_kernel(const float* __restrict__ U)
{
    __shared__ __align__(16) float hbuf[2][HID];
    __shared__ float gpart[4][128];

    const int tid  = threadIdx.x;
    const int lane = tid & 31;
    const int w    = tid >> 5;
    uint32_t rank;
    asm("mov.u32 %0, %%cluster_ctarank;" : "=r"(rank));
    const int b    = blockIdx.x >> 3;
    const int H_lo = (int)rank * 32;

    const int p    = w & 3;          // K quarter (uniform within warp)
    const int gate = w >> 2;         // 0:i 1:f 2:g 3:o
    const int j    = gate * 32 + lane;          // local gate col 0..127
    const int gcol = gate * HID + H_lo + lane;  // global gate col

    // U column slice in registers (64 per thread)
    float u[64];
    #pragma unroll
    for (int i = 0; i < 64; i++)
        u[i] = U[(size_t)(p * 64 + i) * G4 + gcol];

    // zero both h slots (2*256 floats; one per thread)
    reinterpret_cast<float*>(hbuf)[tid] = 0.f;

    const uint32_t hb = smem_u32(&hbuf[0][0]);

    float xw_next = 0.f;
    const float* xwb = &g_xw[(size_t)b * SEQ * G4 + gcol];
    if (p == 0) xw_next = __ldg(xwb);

    // all CTAs' hbuf init visible before any remote writes
    asm volatile("barrier.cluster.arrive.aligned;" ::: "memory");
    asm volatile("barrier.cluster.wait.aligned;"   ::: "memory");

    float c_reg = 0.f;    // cell state (warp0, lane = unit)

    for (int t = 0; t < SEQ; t++) {
        float xw_cur = xw_next;
        if (p == 0 && t + 1 < SEQ)
            xw_next = __ldg(xwb + (size_t)(t + 1) * G4);

        // dot over this warp's K quarter; all lanes read SAME address
        // (LDS broadcast, conflict-free)
        const float4* h4 =
            reinterpret_cast<const float4*>(&hbuf[t & 1][p * 64]);
        float a0 = 0.f, a1 = 0.f, a2 = 0.f, a3 = 0.f;
        #pragma unroll
        for (int i = 0; i < 16; i++) {
            float4 hv = h4[i];
            a0 += hv.x * u[4 * i + 0];
            a1 += hv.y * u[4 * i + 1];
            a2 += hv.z * u[4 * i + 2];
            a3 += hv.w * u[4 * i + 3];
        }
        float acc = (a0 + a1) + (a2 + a3);
        if (p == 0) acc += xw_cur;
        gpart[p][j] = acc;
        __syncthreads();

        if (tid < 32) {
            float gi = gpart[0][lane]      + gpart[1][lane]
                     + gpart[2][lane]      + gpart[3][lane];
            float gf = gpart[0][32 + lane] + gpart[1][32 + lane]
                     + gpart[2][32 + lane] + gpart[3][32 + lane];
            float gg = gpart[0][64 + lane] + gpart[1][64 + lane]
                     + gpart[2][64 + lane] + gpart[3][64 + lane];
            float go = gpart[0][96 + lane] + gpart[1][96 + lane]
                     + gpart[2][96 + lane] + gpart[3][96 + lane];
            float iv = fsigmoid(gi);
            float fv = fsigmoid(gf);
            float gv = ftanh(gg);
            float ov = fsigmoid(go);
            c_reg = fv * c_reg + iv * gv;
            float hv = ov * ftanh(c_reg);

            // persist hidden as bf16 hi/lo for the tensor-core GEMM
            size_t o = ((size_t)b * SEQ + t) * HID + H_lo + lane;
            __nv_bfloat16 hbb = __float2bfloat16(hv);
            g_ahi[o] = hbb;
            g_alo[o] = __float2bfloat16(hv - __bfloat162float(hbb));

            // broadcast h slice to all 8 CTAs' next-step buffer
            if (t + 1 < SEQ) {
                uint32_t laddr =
                    hb + (uint32_t)(((( t + 1) & 1) * HID + H_lo + lane) * 4);
                uint32_t hbits = __float_as_uint(hv);
                #pragma unroll
                for (int r = 0; r < 8; r++) {
                    uint32_t raddr;
                    asm volatile("mapa.shared::cluster.u32 %0, %1, %2;"
                                 : "=r"(raddr) : "r"(laddr), "r"(r));
                    asm volatile("st.shared::cluster.b32 [%0], %1;"
                                 :: "r"(raddr), "r"(hbits) : "memory");
                }
            }
        }
        // cluster barrier publishes h slices; also WAR-protects gpart/hbuf
        asm volatile("barrier.cluster.arrive.aligned;" ::: "memory");
        asm volatile("barrier.cluster.wait.aligned;"   ::: "memory");
    }
}

// ---------------------------------------------------------------------------
// Kernel C: out projection via mma.sync bf16 HMMA + cp.async 2-stage pipeline.
// C = A(8192x256) @ B^T(32000x256) + bias, hi/lo 3-term split, fp32 accum.
// CTA tile 128x128, 8 warps (4x2), warp tile 32x64, K chunks of 32, 2 stages.
// ---------------------------------------------------------------------------
#define SA_HI 0
#define SA_LO 10240
#define SB_HI 20480
#define SB_LO 30720
#define STAGE 40960
#define SPITCH 80     // 32 bf16 (64B) + 16B pad

__device__ __forceinline__ void ldm_x4(uint32_t* r, uint32_t addr) {
    asm volatile("ldmatrix.sync.aligned.m8n8.x4.shared.b16 {%0,%1,%2,%3}, [%4];"
        : "=r"(r[0]), "=r"(r[1]), "=r"(r[2]), "=r"(r[3]) : "r"(addr));
}
__device__ __forceinline__ void mma16816(float* c, const uint32_t* a,
                                         uint32_t b0, uint32_t b1) {
    asm volatile("mma.sync.aligned.m16n8k16.row.col.f32.bf16.bf16.f32 "
        "{%0,%1,%2,%3}, {%4,%5,%6,%7}, {%8,%9}, {%0,%1,%2,%3};"
        : "+f"(c[0]), "+f"(c[1]), "+f"(c[2]), "+f"(c[3])
        : "r"(a[0]), "r"(a[1]), "r"(a[2]), "r"(a[3]), "r"(b0), "r"(b1));
}
__device__ __forceinline__ void cpa16(uint32_t dst, const void* src) {
    asm volatile("cp.async.cg.shared.global [%0], [%1], 16;"
        :: "r"(dst), "l"(src));
}
__device__ __forceinline__ void cpa_commit() {
    asm volatile("cp.async.commit_group;" ::: "memory");
}
template<int N> __device__ __forceinline__ void cpa_wait() {
    asm volatile("cp.async.wait_group %0;" :: "n"(N) : "memory");
}

__global__ __launch_bounds__(256) void out_gemm_mma(
    const float* __restrict__ blin, float* __restrict__ C)
{
    extern __shared__ __align__(16) char smem[];
    const uint32_t sb = smem_u32(smem);
    const int tid  = threadIdx.x;
    const int wid  = tid >> 5, lane = tid & 31;
    const int m0   = blockIdx.x * 128;   // M fastest -> B tile L2-resident
    const int n0   = blockIdx.y * 128;
    const int wm   = (wid & 3) * 32;
    const int wn   = (wid >> 2) * 64;

    // per-thread load coords (128 rows x 4 x 16B per array, 2 chunks/thread)
    const int lrow0 = tid >> 2, lslot = tid & 3;   // chunk q adds 64 rows
    const __nv_bfloat16* aHi = g_ahi  + (size_t)m0 * HID;
    const __nv_bfloat16* aLo = g_alo  + (size_t)m0 * HID;
    const __nv_bfloat16* bHi = g_bhiT + (size_t)n0 * HID;
    const __nv_bfloat16* bLo = g_bloT + (size_t)n0 * HID;

    float c[2][8][4];
    #pragma unroll
    for (int mi = 0; mi < 2; mi++)
        #pragma unroll
        for (int nt = 0; nt < 8; nt++)
            #pragma unroll
            for (int q = 0; q < 4; q++) c[mi][nt][q] = 0.f;

    const int lr = lane & 15;
    const int lc = (lane >> 4) * 8;

    // ---- issue stage 0 ----
    {
        uint32_t base = sb;
        #pragma unroll
        for (int q = 0; q < 2; q++) {
            int row = lrow0 + q * 64;
            uint32_t d = base + (uint32_t)(row * SPITCH + lslot * 16);
            size_t off = (size_t)row * HID + lslot * 8;
            cpa16(d + SA_HI, aHi + off);
            cpa16(d + SA_LO, aLo + off);
            cpa16(d + SB_HI, bHi + off);
            cpa16(d + SB_LO, bLo + off);
        }
        cpa_commit();
    }

    for (int kt = 0; kt < 8; kt++) {
        if (kt < 7) {
            uint32_t base = sb + ((kt + 1) & 1) * STAGE;
            #pragma unroll
            for (int q = 0; q < 2; q++) {
                int row = lrow0 + q * 64;
                uint32_t d = base + (uint32_t)(row * SPITCH + lslot * 16);
                size_t off = (size_t)row * HID + (kt + 1) * 32 + lslot * 8;
                cpa16(d + SA_HI, aHi + off);
                cpa16(d + SA_LO, aLo + off);
                cpa16(d + SB_HI, bHi + off);
                cpa16(d + SB_LO, bLo + off);
            }
            cpa_commit();
            cpa_wait<1>();      // stage kt complete
        } else {
            cpa_wait<0>();
        }
        __syncthreads();

        const uint32_t stg = sb + (kt & 1) * STAGE;
        #pragma unroll
        for (int ks = 0; ks < 2; ks++) {
            const int k0 = ks * 16;
            uint32_t a_hi[2][4], a_lo[2][4];
            #pragma unroll
            for (int mi = 0; mi < 2; mi++) {
                uint32_t ad = stg + SA_HI +
                    (uint32_t)((wm + mi * 16 + lr) * SPITCH + (k0 + lc) * 2);
                ldm_x4(a_hi[mi], ad);
                ldm_x4(a_lo[mi], ad + (SA_LO - SA_HI));
            }
            uint32_t b_hi[4][4], b_lo[4][4];
            #pragma unroll
            for (int nj = 0; nj < 4; nj++) {
                uint32_t bd = stg + SB_HI +
                    (uint32_t)((wn + nj * 16 + lr) * SPITCH + (k0 + lc) * 2);
                ldm_x4(b_hi[nj], bd);
                ldm_x4(b_lo[nj], bd + (SB_LO - SB_HI));
            }
            #pragma unroll
            for (int mi = 0; mi < 2; mi++) {
                #pragma unroll
                for (int nj = 0; nj < 4; nj++) {
                    mma16816(c[mi][2*nj],   a_hi[mi], b_hi[nj][0], b_hi[nj][2]);
                    mma16816(c[mi][2*nj],   a_hi[mi], b_lo[nj][0], b_lo[nj][2]);
                    mma16816(c[mi][2*nj],   a_lo[mi], b_hi[nj][0], b_hi[nj][2]);
                    mma16816(c[mi][2*nj+1], a_hi[mi], b_hi[nj][1], b_hi[nj][3]);
                    mma16816(c[mi][2*nj+1], a_hi[mi], b_lo[nj][1], b_lo[nj][3]);
                    mma16816(c[mi][2*nj+1], a_lo[mi], b_hi[nj][1], b_hi[nj][3]);
                }
            }
        }
        __syncthreads();
    }

    // Epilogue: direct register->gmem
    const int rbase = m0 + wm + (lane >> 2);
    const int cbase = n0 + wn + (lane & 3) * 2;
    #pragma unroll
    for (int mi = 0; mi < 2; mi++) {
        #pragma unroll
        for (int nt = 0; nt < 8; nt++) {
            int col = cbase + nt * 8;
            float2 bb = *reinterpret_cast<const float2*>(&blin[col]);
            int r0 = rbase + mi * 16;
            float2 v0, v1;
            v0.x = c[mi][nt][0] + bb.x; v0.y = c[mi][nt][1] + bb.y;
            v1.x = c[mi][nt][2] + bb.x; v1.y = c[mi][nt][3] + bb.y;
            *reinterpret_cast<float2*>(&C[(size_t)r0 * VOCAB + col]) = v0;
            *reinterpret_cast<float2*>(&C[(size_t)(r0 + 8) * VOCAB + col]) = v1;
        }
    }
}

// ---------------------------------------------------------------------------
extern "C" void kernel_launch(void* const* d_in, const int* in_sizes, int n_in,
                              void* d_out, int out_size)
{
    const int*   sentence = (const int*)  d_in[0];
    const float* emb      = (const float*)d_in[1];
    const float* W        = (const float*)d_in[2];
    const float* U        = (const float*)d_in[3];
    const float* bias     = (const float*)d_in[4];
    const float* wlin     = (const float*)d_in[5];
    const float* blin     = (const float*)d_in[6];
    float* out = (float*)d_out;
    (void)in_sizes; (void)n_in; (void)out_size;

    cudaFuncSetAttribute(out_gemm_mma,
                         cudaFuncAttributeMaxDynamicSharedMemorySize,
                         2 * STAGE);

    // A: embed + xW + bias -> g_xw
    embed_xw_kernel<<<dim3(G4 / 128, TOK / 64), 256>>>(sentence, emb, W, bias);

    // A2: w_linear transpose + bf16 split
    conv_wT_kernel<<<dim3(VOCAB / 32, HID / 32), 256>>>(wlin);

    // B: recurrence -> g_ahi/g_alo (8 clusters of 8 CTAs)
    lstm_kernel<<<64, 512>>>(U);

    // C: pipelined mma.sync output projection + bias -> d_out
    out_gemm_mma<<<dim3(TOK / 128, VOCAB / 128), 256, 2 * STAGE>>>(blin, out);
}